// round 1
// baseline (speedup 1.0000x reference)
#include <cuda_runtime.h>
#include <math.h>

// Problem constants
#define BB 64
#define CC 2048
#define MM 64      // 8*8 pooled positions
#define PP 1000    // 100 classes * 10 protos

// Output segment offsets (floats), tuple order:
// out, contrib, sim_r, cosvalue_u, cosdist_u, maxfs_u, argmaxdist
#define OFF_OUT      0ull
#define OFF_CONTRIB  6400ull
#define OFF_SIM      70400ull
#define OFF_COSV     134400ull
#define OFF_COSD     4230400ull
#define OFF_MAXFS    8326400ull
#define OFF_ARGMAX   139398400ull

// Scratch (device globals: allocation-free rule)
static __device__ float g_fT[(size_t)BB * CC * MM];   // pooled, layout [b][c][m]
static __device__ float g_fN[(size_t)BB * MM * CC];   // normalized, layout [b][m][c]
static __device__ float g_inv_norm[BB * MM];
static __device__ float g_row_scale[BB * MM];
static __device__ float g_col_scale[PP];
static __device__ int   g_amax[BB * PP];

// ---------------------------------------------------------------------------
// 1) Adaptive avg pool 16x16 -> 8x8 (2x2 block means), write fT[b][c][m]
//    grid: B*C/4 blocks, 256 threads; each thread = one (c-plane, m) output.
// ---------------------------------------------------------------------------
__global__ void pool_kernel(const float* __restrict__ x) {
    int t = threadIdx.x;
    int blk = blockIdx.x;                 // 0 .. 32767
    int b = blk >> 9;                      // / (CC/4)
    int cbase = (blk & 511) << 2;
    int plane = t >> 6;                    // 0..3
    int idx = t & 63;                      // m
    int i = idx >> 3, j = idx & 7;
    int c = cbase + plane;
    const float2* x2 = (const float2*)(x + ((size_t)(b * CC + c)) * 256);
    float2 a = x2[(2 * i) * 8 + j];
    float2 d = x2[(2 * i + 1) * 8 + j];
    float v = 0.25f * ((a.x + a.y) + (d.x + d.y));
    g_fT[((size_t)(b * CC + c)) * MM + idx] = v;
}

// ---------------------------------------------------------------------------
// 2) Row norms over c for each (b,m); store inv_norm and row_scale = r1/na
//    grid: 64 (b), block 512 (64 m x 8 c-slices)
// ---------------------------------------------------------------------------
__global__ void norm_kernel() {
    __shared__ float sm[512];
    int b = blockIdx.x;
    int t = threadIdx.x;
    int m = t & 63, sl = t >> 6;
    const float* base = g_fT + (size_t)b * CC * MM + m;
    float acc = 0.f;
    int c0 = sl * 256;
    for (int c = c0; c < c0 + 256; ++c) {
        float v = base[(size_t)c * MM];
        acc += v * v;
    }
    sm[t] = acc;
    __syncthreads();
    for (int s = 256; s >= 64; s >>= 1) {
        if (t < s) sm[t] += sm[t + s];
        __syncthreads();
    }
    if (t < 64) {
        float s1 = sqrtf(sm[t]);
        float r1 = 1.f / fmaxf(s1, 1e-12f);
        float na = s1 * r1 + 1e-3f;        // ||f_norm|| + eps_cos
        g_inv_norm[b * 64 + t] = r1;
        g_row_scale[b * 64 + t] = r1 / na;
    }
}

// ---------------------------------------------------------------------------
// 3) Transpose + normalize: fN[b][m][c] = fT[b][c][m] * inv_norm[b][m]
//    grid: (32 c-tiles, 64 b), block 256; 64x64 smem tile transpose
// ---------------------------------------------------------------------------
__global__ void transpose_kernel() {
    __shared__ float ts[64][65];
    int b = blockIdx.y;
    int cbase = blockIdx.x << 6;
    int t = threadIdx.x;
    int cr = t >> 4;
    int m4 = (t & 15) << 2;
#pragma unroll
    for (int ph = 0; ph < 4; ++ph) {
        int c = cr + ph * 16;
        float4 v = *(const float4*)&g_fT[((size_t)(b * CC + cbase + c)) * MM + m4];
        ts[c][m4 + 0] = v.x; ts[c][m4 + 1] = v.y;
        ts[c][m4 + 2] = v.z; ts[c][m4 + 3] = v.w;
    }
    __syncthreads();
    int c4 = (t & 15) << 2;
#pragma unroll
    for (int ph = 0; ph < 4; ++ph) {
        int m = (t >> 4) + ph * 16;
        float r = g_inv_norm[b * 64 + m];
        float4 o;
        o.x = ts[c4 + 0][m] * r; o.y = ts[c4 + 1][m] * r;
        o.z = ts[c4 + 2][m] * r; o.w = ts[c4 + 3][m] * r;
        *(float4*)&g_fN[((size_t)(b * MM + m)) * CC + cbase + c4] = o;
    }
}

// ---------------------------------------------------------------------------
// 4) Prototype column norms over c; col_scale[p] = r1/nb
//    grid: 16 blocks (64 p each), block 256 (64 p x 4 c-slices of 512)
// ---------------------------------------------------------------------------
__global__ void proto_norm_kernel(const float* __restrict__ proto) {
    __shared__ float sm[256];
    int t = threadIdx.x;
    int p = (blockIdx.x << 6) + (t & 63);
    int sl = t >> 6;
    float acc = 0.f;
    if (p < PP) {
        int c0 = sl * 512;
        for (int c = c0; c < c0 + 512; ++c) {
            float v = proto[(size_t)c * PP + p];
            acc += v * v;
        }
    }
    sm[t] = acc;
    __syncthreads();
    if (t < 128) sm[t] += sm[t + 128];
    __syncthreads();
    if (t < 64 && p < PP) {
        float s1 = sqrtf(sm[t] + sm[t + 64]);
        float r1 = 1.f / fmaxf(s1, 1e-12f);
        float nb = s1 * r1 + 1e-3f;
        g_col_scale[p] = r1 / nb;
    }
}

// ---------------------------------------------------------------------------
// 5) GEMM: cossim[b][m][p] = row_scale*col_scale * dot(fT[b][:,m], proto[:,p])
//    Per block: full M=64 x TN=128 tile, K=2048 in TK=16 chunks, dbl-buffered.
//    Inner loop uses packed fma.rn.f32x2 (2 fp32 FMA / inst) — FFMA is rt=2
//    on sm_103a, FFMA2 doubles fma-pipe throughput.
//    Epilogue writes cosvalue_u and cosdist_u directly into d_out.
// ---------------------------------------------------------------------------
__global__ __launch_bounds__(256) void gemm_kernel(const float* __restrict__ proto,
                                                   float* __restrict__ dout) {
    __shared__ float As[2][16][64];
    __shared__ float Bs[2][16][128];
    int b = blockIdx.y;
    int p0 = blockIdx.x << 7;
    int t = threadIdx.x;
    int tx = t & 31, ty = t >> 5;          // tx -> p (32*4), ty -> m (8*8)
    const float* gA = g_fT + (size_t)b * CC * MM;

    unsigned long long acc2[4][4];         // packed pairs over m: (m0,m1)
#pragma unroll
    for (int i = 0; i < 4; ++i)
#pragma unroll
        for (int j = 0; j < 4; ++j) acc2[i][j] = 0ull;

    int ca = t >> 4, ma = (t & 15) << 2;   // A tile load coords
    int cbth = t >> 6;                     // B tile load coords
    int pth = (t & 63) << 1;

    // prefetch tile 0
    {
        float4 av = *(const float4*)&gA[(size_t)ca * MM + ma];
        *(float4*)&As[0][ca][ma] = av;
#pragma unroll
        for (int ph = 0; ph < 4; ++ph) {
            int cb = cbth + ph * 4;
            float2 bv = make_float2(0.f, 0.f);
            int pp = p0 + pth;
            if (pp < PP) bv = *(const float2*)&proto[(size_t)cb * PP + pp];
            *(float2*)&Bs[0][cb][pth] = bv;
        }
    }

    int buf = 0;
    for (int kt = 0; kt < 128; ++kt) {
        __syncthreads();
        if (kt < 127) {
            int c0 = (kt + 1) * 16;
            float4 av = *(const float4*)&gA[(size_t)(c0 + ca) * MM + ma];
            *(float4*)&As[buf ^ 1][ca][ma] = av;
#pragma unroll
            for (int ph = 0; ph < 4; ++ph) {
                int cb = cbth + ph * 4;
                float2 bv = make_float2(0.f, 0.f);
                int pp = p0 + pth;
                if (pp < PP) bv = *(const float2*)&proto[(size_t)(c0 + cb) * PP + pp];
                *(float2*)&Bs[buf ^ 1][cb][pth] = bv;
            }
        }
#pragma unroll
        for (int k = 0; k < 16; ++k) {
            float4 a0 = *(const float4*)&As[buf][k][ty * 8];
            float4 a1 = *(const float4*)&As[buf][k][ty * 8 + 4];
            float4 b4 = *(const float4*)&Bs[buf][k][tx * 4];
            unsigned long long ap[4], bp[4];
            asm("mov.b64 %0, {%1, %2};" : "=l"(ap[0]) : "r"(__float_as_uint(a0.x)), "r"(__float_as_uint(a0.y)));
            asm("mov.b64 %0, {%1, %2};" : "=l"(ap[1]) : "r"(__float_as_uint(a0.z)), "r"(__float_as_uint(a0.w)));
            asm("mov.b64 %0, {%1, %2};" : "=l"(ap[2]) : "r"(__float_as_uint(a1.x)), "r"(__float_as_uint(a1.y)));
            asm("mov.b64 %0, {%1, %2};" : "=l"(ap[3]) : "r"(__float_as_uint(a1.z)), "r"(__float_as_uint(a1.w)));
            asm("mov.b64 %0, {%1, %1};" : "=l"(bp[0]) : "r"(__float_as_uint(b4.x)));
            asm("mov.b64 %0, {%1, %1};" : "=l"(bp[1]) : "r"(__float_as_uint(b4.y)));
            asm("mov.b64 %0, {%1, %1};" : "=l"(bp[2]) : "r"(__float_as_uint(b4.z)));
            asm("mov.b64 %0, {%1, %1};" : "=l"(bp[3]) : "r"(__float_as_uint(b4.w)));
#pragma unroll
            for (int i = 0; i < 4; ++i)
#pragma unroll
                for (int j = 0; j < 4; ++j)
                    asm("fma.rn.f32x2 %0, %1, %2, %0;"
                        : "+l"(acc2[i][j]) : "l"(ap[i]), "l"(bp[j]));
        }
        buf ^= 1;
    }

    // epilogue: scale + write cosvalue / cosdist
    float rs[8];
#pragma unroll
    for (int i = 0; i < 8; ++i) rs[i] = g_row_scale[b * 64 + ty * 8 + i];
#pragma unroll
    for (int j = 0; j < 4; ++j) {
        int p = p0 + tx * 4 + j;
        if (p < PP) {
            float cs = g_col_scale[p];
            size_t rbase = (size_t)b * 64000 + (size_t)p * 64 + (size_t)(ty * 8);
#pragma unroll
            for (int i2 = 0; i2 < 4; ++i2) {
                unsigned int lo, hi;
                asm("mov.b64 {%0, %1}, %2;" : "=r"(lo), "=r"(hi) : "l"(acc2[i2][j]));
                float v0 = __uint_as_float(lo) * rs[i2 * 2] * cs;
                float v1 = __uint_as_float(hi) * rs[i2 * 2 + 1] * cs;
                dout[OFF_COSV + rbase + i2 * 2] = v0;
                dout[OFF_COSV + rbase + i2 * 2 + 1] = v1;
                dout[OFF_COSD + rbase + i2 * 2] = 1.f - v0;
                dout[OFF_COSD + rbase + i2 * 2 + 1] = 1.f - v1;
            }
        }
    }
}

// ---------------------------------------------------------------------------
// 6) max/argmax over m (64) per (b,p); writes sim_r, contrib, argmax (float),
//    and int argmax to scratch. One warp per (b,p) pair.
// ---------------------------------------------------------------------------
__global__ void max_kernel(const float* __restrict__ weight,
                           const float* __restrict__ weight_e,
                           float* __restrict__ dout) {
    int t = threadIdx.x;
    int pair = (blockIdx.x << 3) + (t >> 5);  // 0 .. 63999
    int lane = t & 31;
    const float* base = dout + OFF_COSV + (size_t)pair * 64;
    float v0 = base[lane], v1 = base[lane + 32];
    float val; int idx;
    if (v1 > v0) { val = v1; idx = lane + 32; } else { val = v0; idx = lane; }
#pragma unroll
    for (int off = 16; off; off >>= 1) {
        float ov = __shfl_down_sync(0xffffffffu, val, off);
        int   oi = __shfl_down_sync(0xffffffffu, idx, off);
        if (ov > val || (ov == val && oi < idx)) { val = ov; idx = oi; }
    }
    if (lane == 0) {
        int p = pair % 1000;
        dout[OFF_SIM + pair] = val;
        float w = weight[p], we = weight_e[p];
        float sg = 1.f / (1.f + expf(-we));
        dout[OFF_CONTRIB + pair] = val * w * sg;
        dout[OFF_ARGMAX + pair] = (float)idx;
        g_amax[pair] = idx;
    }
}

// ---------------------------------------------------------------------------
// 7) out[b][nc] = sum over npr of contrib
// ---------------------------------------------------------------------------
__global__ void outsum_kernel(float* __restrict__ dout) {
    int id = blockIdx.x * 256 + threadIdx.x;
    if (id >= 6400) return;
    const float* c = dout + OFF_CONTRIB + (size_t)id * 10;
    float s = 0.f;
#pragma unroll
    for (int q = 0; q < 10; ++q) s += c[q];
    dout[OFF_OUT + id] = s;
}

// ---------------------------------------------------------------------------
// 8) maxfs gather: copy the argmax'd normalized f row (2048 floats) per (b,p).
//    Streaming stores (no reuse of the 524 MB output).
// ---------------------------------------------------------------------------
__global__ void gather_kernel(float* __restrict__ dout) {
    int p = blockIdx.x, b = blockIdx.y;
    int pair = b * 1000 + p;
    int m = g_amax[pair];
    const float4* src = (const float4*)(g_fN + ((size_t)(b * 64 + m)) * CC);
    float4* dst = (float4*)(dout + OFF_MAXFS + (size_t)pair * CC);
    int t = threadIdx.x;
    float4 v0 = src[t];
    float4 v1 = src[t + 256];
    __stcs(&dst[t], v0);
    __stcs(&dst[t + 256], v1);
}

// ---------------------------------------------------------------------------
extern "C" void kernel_launch(void* const* d_in, const int* in_sizes, int n_in,
                              void* d_out, int out_size) {
    const float* x     = (const float*)d_in[0];
    const float* proto = (const float*)d_in[1];
    const float* w     = (const float*)d_in[2];
    const float* we    = (const float*)d_in[3];
    float* out = (float*)d_out;

    pool_kernel<<<32768, 256>>>(x);
    norm_kernel<<<64, 512>>>();
    transpose_kernel<<<dim3(32, 64), 256>>>();
    proto_norm_kernel<<<16, 256>>>(proto);
    gemm_kernel<<<dim3(8, 64), 256>>>(proto, out);
    max_kernel<<<8000, 256>>>(w, we, out);
    outsum_kernel<<<25, 256>>>(out);
    gather_kernel<<<dim3(1000, 64), 256>>>(out);
}